// round 3
// baseline (speedup 1.0000x reference)
#include <cuda_runtime.h>

#define Hdim 1024
#define Wdim 1024
#define HWdim (Hdim * Wdim)
#define TS 32
#define NT 256

__device__ __forceinline__ float sigmoidf_(float y) {
    return 1.0f / (1.0f + __expf(-y));
}

__global__ __launch_bounds__(NT, 2) void unet_fused_kernel(
    const float* __restrict__ x,  const float* __restrict__ x2,
    const float* __restrict__ w1a, const float* __restrict__ b1a,
    const float* __restrict__ w2a, const float* __restrict__ b2a,
    const float* __restrict__ w3a, const float* __restrict__ b3a,
    const float* __restrict__ w1b, const float* __restrict__ b1b,
    const float* __restrict__ w2b, const float* __restrict__ b2b,
    const float* __restrict__ w3b, const float* __restrict__ b3b,
    const float* __restrict__ lw1, const float* __restrict__ lb1,
    const float* __restrict__ lw2, const float* __restrict__ lb2,
    float* __restrict__ outf, float* __restrict__ den1, float* __restrict__ den2)
{
    __shared__ float s_x[3][38][38];   // input tile, 3-halo
    __shared__ float s_c4[36][36];     // conv1 out, 2-halo
    __shared__ float s_c5[34][34];     // conv2 out, 1-halo
    __shared__ float s_M[12];          // folded 6->2 matrix
    __shared__ float s_B2[2];

    const int tid = threadIdx.x;
    const int h0  = blockIdx.y * TS;
    const int w0  = blockIdx.x * TS;

    // Fold MLP (no inner nonlinearity): M = lw2@lw1, B = lw2@lb1 + lb2.
    // Redundant per block, trivial cost, overlaps the tile load below.
    if (tid < 12) {
        int o = tid / 6, c = tid % 6;
        float acc = 0.0f;
        #pragma unroll 4
        for (int k = 0; k < 128; k++)
            acc += __ldg(&lw2[o * 128 + k]) * __ldg(&lw1[k * 6 + c]);
        s_M[tid] = acc;
    } else if (tid < 14) {
        int o = tid - 12;
        float acc = __ldg(&lb2[o]);
        #pragma unroll 4
        for (int k = 0; k < 128; k++)
            acc += __ldg(&lw2[o * 128 + k]) * __ldg(&lb1[k]);
        s_B2[o] = acc;
    }

    float fa[4][6];  // encoder-a features for this thread's 4 pixels

    #pragma unroll 1
    for (int e = 0; e < 2; e++) {
        const float* X   = e ? x2  : x;
        const float* W1  = e ? w1b : w1a;
        const float* W2  = e ? w2b : w2a;
        const float* W3  = e ? w3b : w3a;
        const float* B1  = e ? b1b : b1a;
        const float* Bc2 = e ? b2b : b2a;
        const float* B3  = e ? b3b : b3a;
        float* den = e ? den2 : den1;

        __syncthreads();  // protect smem reuse across encoders

        // ---- load input tile (3 ch, 3-halo, zero padded) ----
        #pragma unroll 1
        for (int c = 0; c < 3; c++) {
            #pragma unroll 1
            for (int idx = tid; idx < 38 * 38; idx += NT) {
                int r = idx / 38;
                int q = idx - r * 38;
                int gh = h0 - 3 + r, gw = w0 - 3 + q;
                float v = 0.0f;
                if ((unsigned)gh < (unsigned)Hdim && (unsigned)gw < (unsigned)Wdim)
                    v = __ldg(&X[c * HWdim + gh * Wdim + gw]);
                s_x[c][r][q] = v;
            }
        }
        __syncthreads();

        // ================= conv1: 3ch -> c4 over 36x36 =================
        // Outside-image positions must be 0 (reference zero-pads the
        // concatenated tensor).
        {
            float w[27];
            #pragma unroll
            for (int k = 0; k < 27; k++) w[k] = __ldg(&W1[k]);
            const float b = __ldg(&B1[0]);

            #pragma unroll 1
            for (int s = tid; s < 36 * 9; s += NT) {
                int sr  = s / 36;
                int col = s - sr * 36;
                int j0  = sr * 4;
                float a[4] = {b, b, b, b};
                #pragma unroll
                for (int c = 0; c < 3; c++) {
                    #pragma unroll
                    for (int jj = 0; jj < 6; jj++) {
                        float t0 = s_x[c][j0 + jj][col];
                        float t1 = s_x[c][j0 + jj][col + 1];
                        float t2 = s_x[c][j0 + jj][col + 2];
                        #pragma unroll
                        for (int r = 0; r < 4; r++) {
                            int kh = jj - r;
                            if (kh >= 0 && kh < 3)
                                a[r] += w[c*9 + kh*3 + 0] * t0
                                      + w[c*9 + kh*3 + 1] * t1
                                      + w[c*9 + kh*3 + 2] * t2;
                        }
                    }
                }
                int gw = w0 + col - 2;
                bool wi = (unsigned)gw < (unsigned)Wdim;
                #pragma unroll
                for (int r = 0; r < 4; r++) {
                    int gh = h0 + j0 + r - 2;
                    s_c4[j0 + r][col] =
                        (wi && (unsigned)gh < (unsigned)Hdim) ? sigmoidf_(a[r]) : 0.0f;
                }
            }
        }
        __syncthreads();

        // ================= conv2: [x,c4] -> c5 over 34x34 =================
        {
            float w[36];
            #pragma unroll
            for (int k = 0; k < 36; k++) w[k] = __ldg(&W2[k]);
            const float b = __ldg(&Bc2[0]);

            #pragma unroll 1
            for (int s = tid; s < 34 * 9; s += NT) {
                int sr  = s / 34;
                int col = s - sr * 34;
                int j0  = sr * 4;
                if (j0 > 30) j0 = 30;   // clamp: rows 30,31 computed twice (same value)
                float a[4] = {b, b, b, b};
                #pragma unroll
                for (int c = 0; c < 3; c++) {
                    #pragma unroll
                    for (int jj = 0; jj < 6; jj++) {
                        float t0 = s_x[c][j0 + jj + 1][col + 1];
                        float t1 = s_x[c][j0 + jj + 1][col + 2];
                        float t2 = s_x[c][j0 + jj + 1][col + 3];
                        #pragma unroll
                        for (int r = 0; r < 4; r++) {
                            int kh = jj - r;
                            if (kh >= 0 && kh < 3)
                                a[r] += w[c*9 + kh*3 + 0] * t0
                                      + w[c*9 + kh*3 + 1] * t1
                                      + w[c*9 + kh*3 + 2] * t2;
                        }
                    }
                }
                #pragma unroll
                for (int jj = 0; jj < 6; jj++) {
                    float t0 = s_c4[j0 + jj][col];
                    float t1 = s_c4[j0 + jj][col + 1];
                    float t2 = s_c4[j0 + jj][col + 2];
                    #pragma unroll
                    for (int r = 0; r < 4; r++) {
                        int kh = jj - r;
                        if (kh >= 0 && kh < 3)
                            a[r] += w[27 + kh*3 + 0] * t0
                                  + w[27 + kh*3 + 1] * t1
                                  + w[27 + kh*3 + 2] * t2;
                    }
                }
                int gw = w0 + col - 1;
                bool wi = (unsigned)gw < (unsigned)Wdim;
                #pragma unroll
                for (int r = 0; r < 4; r++) {
                    int gh = h0 + j0 + r - 1;
                    s_c5[j0 + r][col] =
                        (wi && (unsigned)gh < (unsigned)Hdim) ? sigmoidf_(a[r]) : 0.0f;
                }
            }
        }
        __syncthreads();

        // ========= conv3: [x,c4,c5] -> c6 + outputs, 32x32 (1 strip/thread) =========
        {
            float w[45];
            #pragma unroll
            for (int k = 0; k < 45; k++) w[k] = __ldg(&W3[k]);
            const float b = __ldg(&B3[0]);

            const int col = tid & 31;
            const int j0  = (tid >> 5) * 4;
            float a[4] = {b, b, b, b};

            #pragma unroll
            for (int c = 0; c < 3; c++) {
                #pragma unroll
                for (int jj = 0; jj < 6; jj++) {
                    float t0 = s_x[c][j0 + jj + 2][col + 2];
                    float t1 = s_x[c][j0 + jj + 2][col + 3];
                    float t2 = s_x[c][j0 + jj + 2][col + 4];
                    #pragma unroll
                    for (int r = 0; r < 4; r++) {
                        int kh = jj - r;
                        if (kh >= 0 && kh < 3)
                            a[r] += w[c*9 + kh*3 + 0] * t0
                                  + w[c*9 + kh*3 + 1] * t1
                                  + w[c*9 + kh*3 + 2] * t2;
                    }
                }
            }
            #pragma unroll
            for (int jj = 0; jj < 6; jj++) {
                float t0 = s_c4[j0 + jj + 1][col + 1];
                float t1 = s_c4[j0 + jj + 1][col + 2];
                float t2 = s_c4[j0 + jj + 1][col + 3];
                #pragma unroll
                for (int r = 0; r < 4; r++) {
                    int kh = jj - r;
                    if (kh >= 0 && kh < 3)
                        a[r] += w[27 + kh*3 + 0] * t0
                              + w[27 + kh*3 + 1] * t1
                              + w[27 + kh*3 + 2] * t2;
                }
            }
            #pragma unroll
            for (int jj = 0; jj < 6; jj++) {
                float t0 = s_c5[j0 + jj][col];
                float t1 = s_c5[j0 + jj][col + 1];
                float t2 = s_c5[j0 + jj][col + 2];
                #pragma unroll
                for (int r = 0; r < 4; r++) {
                    int kh = jj - r;
                    if (kh >= 0 && kh < 3)
                        a[r] += w[36 + kh*3 + 0] * t0
                              + w[36 + kh*3 + 1] * t1
                              + w[36 + kh*3 + 2] * t2;
                }
            }

            #pragma unroll
            for (int r = 0; r < 4; r++) {
                int j = j0 + r;
                float f5 = sigmoidf_(a[r]);
                float f0 = s_x[0][j + 3][col + 3];
                float f1 = s_x[1][j + 3][col + 3];
                float f2 = s_x[2][j + 3][col + 3];
                float f3 = s_c4[j + 2][col + 2];
                float f4 = s_c5[j + 1][col + 1];

                int pix = (h0 + j) * Wdim + (w0 + col);
                float2* dp = (float2*)(den + (size_t)pix * 6);
                dp[0] = make_float2(f0, f1);
                dp[1] = make_float2(f2, f3);
                dp[2] = make_float2(f4, f5);

                if (e == 0) {
                    fa[r][0] = f0; fa[r][1] = f1; fa[r][2] = f2;
                    fa[r][3] = f3; fa[r][4] = f4; fa[r][5] = f5;
                } else {
                    float d0 = fa[r][0] - f0, d1 = fa[r][1] - f1, d2 = fa[r][2] - f2;
                    float d3 = fa[r][3] - f3, d4 = fa[r][4] - f4, d5 = fa[r][5] - f5;
                    float o0 = s_B2[0] + s_M[0]*d0 + s_M[1]*d1 + s_M[2]*d2
                                       + s_M[3]*d3 + s_M[4]*d4 + s_M[5]*d5;
                    float o1 = s_B2[1] + s_M[6]*d0 + s_M[7]*d1 + s_M[8]*d2
                                       + s_M[9]*d3 + s_M[10]*d4 + s_M[11]*d5;
                    ((float2*)outf)[pix] = make_float2(o0, o1);
                }
            }
        }
    }
}

extern "C" void kernel_launch(void* const* d_in, const int* in_sizes, int n_in,
                              void* d_out, int out_size) {
    const float* x   = (const float*)d_in[0];
    const float* x2  = (const float*)d_in[1];
    const float* w1a = (const float*)d_in[2];
    const float* b1a = (const float*)d_in[3];
    const float* w2a = (const float*)d_in[4];
    const float* b2a = (const float*)d_in[5];
    const float* w3a = (const float*)d_in[6];
    const float* b3a = (const float*)d_in[7];
    const float* w1b = (const float*)d_in[8];
    const float* b1b = (const float*)d_in[9];
    const float* w2b = (const float*)d_in[10];
    const float* b2b = (const float*)d_in[11];
    const float* w3b = (const float*)d_in[12];
    const float* b3b = (const float*)d_in[13];
    const float* lw1 = (const float*)d_in[14];
    const float* lb1 = (const float*)d_in[15];
    const float* lw2 = (const float*)d_in[16];
    const float* lb2 = (const float*)d_in[17];

    float* outf = (float*)d_out;                       // [HW, 2]
    float* den1 = (float*)d_out + (size_t)2 * HWdim;   // [H, W, 6]
    float* den2 = (float*)d_out + (size_t)8 * HWdim;   // [H, W, 6]

    dim3 grid(Wdim / TS, Hdim / TS);
    unet_fused_kernel<<<grid, NT>>>(
        x, x2, w1a, b1a, w2a, b2a, w3a, b3a,
        w1b, b1b, w2b, b2b, w3b, b3b,
        lw1, lb1, lw2, lb2,
        outf, den1, den2);
}